// round 15
// baseline (speedup 1.0000x reference)
#include <cuda_runtime.h>
#include <cstddef>
#include <cstdint>

// LocalAttention: B=4, S=2048, D=256, W=33
// out = [values (B,S,D) | p_attn (B,S,W)] as float32
// Pass 1 (Q.K^T band scores) on TF32 tensor cores; softmax + PV scalar fp32.

#define S_LEN   2048
#define D_DIM   256
#define B_SZ    4
#define W_SZ    33
#define HALF_W  16
#define TILE_Q  64
#define THREADS 512                // 16 warps
#define QW      4                  // queries per softmax/pass2 warp
#define ROWS    (TILE_Q + 2*HALF_W)  // 96 K/V rows
#define NR      (QW + 2*HALF_W)    // 36 rows per pass2 warp
#define NW      (THREADS/32)       // 16 warps

#define QP      260                // padded floats per K/Q/V row (bank-conflict-free frags)
#define QPC     65                 // 16B chunks per padded row
#define SROW    36                 // padded floats per score row

// smem float offsets
#define OFF_K   0                         // K:  96*260
#define OFF_U   (ROWS*QP)                 // Q (64 rows) then V (96 rows)
#define OFF_S   (OFF_U + ROWS*QP)         // scores: 64*36
#define OFF_PF  (OFF_S + TILE_Q*SROW)     // final p: [NW][NR][4]
#define OFF_F   (OFF_PF + NW*NR*4)        // flags: 96 ints
#define SMEM_FLOATS (OFF_F + ROWS)
#define SMEM_BYTES  (SMEM_FLOATS*4)

typedef unsigned long long ull;

__device__ __forceinline__ ull fma2(ull a, ull b, ull c) {
    ull d;
    asm("fma.rn.f32x2 %0, %1, %2, %3;" : "=l"(d) : "l"(a), "l"(b), "l"(c));
    return d;
}
__device__ __forceinline__ ull pack2(float x) {
    ull d;
    asm("mov.b64 %0, {%1, %1};" : "=l"(d) : "f"(x));
    return d;
}
__device__ __forceinline__ uint32_t cvt_tf32(float x) {
    uint32_t r;
    asm("cvt.rna.tf32.f32 %0, %1;" : "=r"(r) : "f"(x));
    return r;
}
__device__ __forceinline__ void mma_tf32(float& c0, float& c1, float& c2, float& c3,
                                         uint32_t a0, uint32_t a1, uint32_t a2, uint32_t a3,
                                         uint32_t b0, uint32_t b1) {
    asm volatile("mma.sync.aligned.m16n8k8.row.col.f32.tf32.tf32.f32 "
                 "{%0,%1,%2,%3}, {%4,%5,%6,%7}, {%8,%9}, {%0,%1,%2,%3};"
                 : "+f"(c0), "+f"(c1), "+f"(c2), "+f"(c3)
                 : "r"(a0), "r"(a1), "r"(a2), "r"(a3), "r"(b0), "r"(b1));
}
__device__ __forceinline__ void cp16(void* smem_dst, const void* gsrc) {
    uint32_t s = (uint32_t)__cvta_generic_to_shared(smem_dst);
    asm volatile("cp.async.cg.shared.global [%0], [%1], 16;" :: "r"(s), "l"(gsrc));
}

__global__ void __launch_bounds__(THREADS, 1)
local_attn_kernel(const float* __restrict__ qg,
                  const float* __restrict__ kg,
                  const float* __restrict__ vg,
                  const int*   __restrict__ maskg,
                  float* __restrict__ out_vals,
                  float* __restrict__ out_p)
{
    extern __shared__ float smem[];
    float4* sm4  = reinterpret_cast<float4*>(smem);
    float*  Ksmf = smem + OFF_K;
    float*  Usmf = smem + OFF_U;
    float*  Sbl  = smem + OFF_S;
    float*  PF   = smem + OFF_PF;
    int*    Fsm  = reinterpret_cast<int*>(smem + OFF_F);

    const int tile = blockIdx.x;
    const int b    = blockIdx.y;
    const int base = tile * TILE_Q;
    const int r0   = base - HALF_W;
    const int tid  = threadIdx.x;

    const float4* kg4 = reinterpret_cast<const float4*>(kg + (size_t)b * S_LEN * D_DIM);
    const float4* vg4 = reinterpret_cast<const float4*>(vg + (size_t)b * S_LEN * D_DIM);
    const float4* qg4 = reinterpret_cast<const float4*>(qg + ((size_t)b * S_LEN + base) * D_DIM);

    // ---- async-stage K (rows clamped) into padded rows ----
    #pragma unroll
    for (int it = 0; it < ROWS * 64 / THREADS; ++it) {   // 12 iters
        int idx  = tid + it * THREADS;
        int row  = idx >> 6;
        int col  = idx & 63;
        int grow = r0 + row;
        int gcl  = grow < 0 ? 0 : (grow >= S_LEN ? S_LEN - 1 : grow);
        cp16(sm4 + row * QPC + col, kg4 + (size_t)gcl * 64 + col);
    }
    // ---- async-stage Q (64 rows, in range) into U region ----
    #pragma unroll
    for (int it = 0; it < TILE_Q * 64 / THREADS; ++it) {  // 8 iters
        int idx = tid + it * THREADS;
        int row = idx >> 6;
        int col = idx & 63;
        cp16(sm4 + (OFF_U / 4) + row * QPC + col, qg4 + (size_t)row * 64 + col);
    }
    asm volatile("cp.async.commit_group;" ::: "memory");

    // ---- mask flags ----
    if (tid < ROWS) {
        int grow = r0 + tid;
        int f = 0;
        if (grow >= 0 && grow < S_LEN) f = (maskg[b * S_LEN + grow] != 0);
        Fsm[tid] = f;
    }

    const int warp = tid >> 5;
    const int lane = tid & 31;
    const int lq0  = warp * QW;
    float* pf = PF + warp * NR * 4;      // this warp's final p [NR][4]

    // zero final-p (out-of-window slots must read 0 in pass 2)
    #pragma unroll
    for (int i = lane; i < NR * 4; i += 32) pf[i] = 0.f;

    asm volatile("cp.async.wait_group 0;" ::: "memory");
    __syncthreads();

    // ---- pass 1: band GEMM on tensor cores ----
    // 24 band tiles: tile t -> qt=t/6, q0=16*qt, n0=16*qt+8*(t%6)
    const int g  = lane >> 2;    // 0..7
    const int t4 = lane & 3;     // 0..3
    #pragma unroll
    for (int ti = 0; ti < 2; ++ti) {
        int t = warp + ti * 16;
        if (t < 24) {
            int qt = t / 6;
            int q0 = qt * 16;
            int n0 = q0 + (t % 6) * 8;
            float c0 = 0.f, c1 = 0.f, c2 = 0.f, c3 = 0.f;
            const float* Qa  = Usmf + (q0 + g) * QP + t4;
            const float* Qa8 = Qa + 8 * QP;
            const float* Kb  = Ksmf + (n0 + g) * QP + t4;
            #pragma unroll 8
            for (int ks = 0; ks < 32; ++ks) {
                int d0 = ks * 8;
                uint32_t a0 = cvt_tf32(Qa[d0]);
                uint32_t a1 = cvt_tf32(Qa8[d0]);
                uint32_t a2 = cvt_tf32(Qa[d0 + 4]);
                uint32_t a3 = cvt_tf32(Qa8[d0 + 4]);
                uint32_t b0 = cvt_tf32(Kb[d0]);
                uint32_t b1 = cvt_tf32(Kb[d0 + 4]);
                mma_tf32(c0, c1, c2, c3, a0, a1, a2, a3, b0, b1);
            }
            // epilogue: scatter band entries with scale + mask
            int q_l = q0 + g;
            int m0  = n0 + 2 * t4;
            int w;
            w = m0 - q_l;
            if (w >= 0 && w <= 32) Sbl[q_l * SROW + w] = Fsm[m0] ? c0 * 0.0625f : -1e10f;
            w = m0 + 1 - q_l;
            if (w >= 0 && w <= 32) Sbl[q_l * SROW + w] = Fsm[m0 + 1] ? c1 * 0.0625f : -1e10f;
            w = m0 - (q_l + 8);
            if (w >= 0 && w <= 32) Sbl[(q_l + 8) * SROW + w] = Fsm[m0] ? c2 * 0.0625f : -1e10f;
            w = m0 + 1 - (q_l + 8);
            if (w >= 0 && w <= 32) Sbl[(q_l + 8) * SROW + w] = Fsm[m0 + 1] ? c3 * 0.0625f : -1e10f;
        }
    }
    __syncthreads();   // scores visible block-wide; Q reads done

    // ---- async-stage V over the Q region ----
    #pragma unroll
    for (int it = 0; it < ROWS * 64 / THREADS; ++it) {   // 12 iters
        int idx  = tid + it * THREADS;
        int row  = idx >> 6;
        int col  = idx & 63;
        int grow = r0 + row;
        int gcl  = grow < 0 ? 0 : (grow >= S_LEN ? S_LEN - 1 : grow);
        cp16(sm4 + (OFF_U / 4) + row * QPC + col, vg4 + (size_t)gcl * 64 + col);
    }
    asm volatile("cp.async.commit_group;" ::: "memory");

    // ---- warp-local softmax: 8 lanes per query (overlaps V flight) ----
    const int g8 = lane >> 3;
    const int j  = lane & 7;
    const int gq = base + lq0 + g8;
    {
        const float* srow = Sbl + (lq0 + g8) * SROW;
        float s0 = srow[j];
        float s1 = srow[j + 8];
        float s2 = srow[j + 16];
        float s3 = srow[j + 24];
        float s4 = (j == 0) ? srow[32] : -3e38f;

        float mx = fmaxf(fmaxf(fmaxf(s0, s1), fmaxf(s2, s3)), s4);
        mx = fmaxf(mx, __shfl_xor_sync(0xffffffffu, mx, 4));
        mx = fmaxf(mx, __shfl_xor_sync(0xffffffffu, mx, 2));
        mx = fmaxf(mx, __shfl_xor_sync(0xffffffffu, mx, 1));

        float e0 = __expf(s0 - mx);
        float e1 = __expf(s1 - mx);
        float e2 = __expf(s2 - mx);
        float e3 = __expf(s3 - mx);
        float e4 = (j == 0) ? __expf(s4 - mx) : 0.f;

        float sum = ((e0 + e1) + (e2 + e3)) + e4;
        sum += __shfl_xor_sync(0xffffffffu, sum, 4);
        sum += __shfl_xor_sync(0xffffffffu, sum, 2);
        sum += __shfl_xor_sync(0xffffffffu, sum, 1);
        float inv = 1.f / sum;

        float p0 = e0 * inv, p1 = e1 * inv, p2 = e2 * inv, p3 = e3 * inv;
        // pf[(g8 + w)*4 + g8] = p_w  (row-indexed for pass 2)
        int m0 = g8 + j;
        pf[m0 * 4 + g8]        = p0;
        pf[(m0 + 8) * 4 + g8]  = p1;
        pf[(m0 + 16) * 4 + g8] = p2;
        pf[(m0 + 24) * 4 + g8] = p3;

        float* po = out_p + (size_t)(b * S_LEN + gq) * W_SZ;
        po[j]      = p0;
        po[j + 8]  = p1;
        po[j + 16] = p2;
        po[j + 24] = p3;
        if (j == 0) {
            float p4 = e4 * inv;
            pf[(g8 + 32) * 4 + g8] = p4;
            po[32] = p4;
        }
    }

    // V resident + visible (and pf published) before pass 2
    asm volatile("cp.async.wait_group 0;" ::: "memory");
    __syncthreads();

    // ---- pass 2: scalar fp32x2, V rows + p float4 prefetched ----
    ulonglong2 acc[QW][2];
    #pragma unroll
    for (int q = 0; q < QW; ++q) {
        acc[q][0].x = 0ull; acc[q][0].y = 0ull;
        acc[q][1].x = 0ull; acc[q][1].y = 0ull;
    }

    const ulonglong2* Vsm2 = reinterpret_cast<const ulonglong2*>(Usmf);
    const float4* pf4 = reinterpret_cast<const float4*>(pf);

    ulonglong2 v0 = Vsm2[(size_t)lq0 * QPC + 2 * lane];
    ulonglong2 v1 = Vsm2[(size_t)lq0 * QPC + 2 * lane + 1];
    float4 pv = pf4[0];

    #pragma unroll 4
    for (int r = 0; r < NR; ++r) {   // 36
        ulonglong2 v0n, v1n;
        float4 pvn;
        if (r + 1 < NR) {
            const ulonglong2* vn = Vsm2 + (size_t)(lq0 + r + 1) * QPC + 2 * lane;
            v0n = vn[0];
            v1n = vn[1];
            pvn = pf4[r + 1];
        }
        ull pp0 = pack2(pv.x);
        ull pp1 = pack2(pv.y);
        ull pp2 = pack2(pv.z);
        ull pp3 = pack2(pv.w);
        acc[0][0].x = fma2(pp0, v0.x, acc[0][0].x);
        acc[0][0].y = fma2(pp0, v0.y, acc[0][0].y);
        acc[0][1].x = fma2(pp0, v1.x, acc[0][1].x);
        acc[0][1].y = fma2(pp0, v1.y, acc[0][1].y);
        acc[1][0].x = fma2(pp1, v0.x, acc[1][0].x);
        acc[1][0].y = fma2(pp1, v0.y, acc[1][0].y);
        acc[1][1].x = fma2(pp1, v1.x, acc[1][1].x);
        acc[1][1].y = fma2(pp1, v1.y, acc[1][1].y);
        acc[2][0].x = fma2(pp2, v0.x, acc[2][0].x);
        acc[2][0].y = fma2(pp2, v0.y, acc[2][0].y);
        acc[2][1].x = fma2(pp2, v1.x, acc[2][1].x);
        acc[2][1].y = fma2(pp2, v1.y, acc[2][1].y);
        acc[3][0].x = fma2(pp3, v0.x, acc[3][0].x);
        acc[3][0].y = fma2(pp3, v0.y, acc[3][0].y);
        acc[3][1].x = fma2(pp3, v1.x, acc[3][1].x);
        acc[3][1].y = fma2(pp3, v1.y, acc[3][1].y);
        v0 = v0n;
        v1 = v1n;
        pv = pvn;
    }

    ulonglong2* obase = reinterpret_cast<ulonglong2*>(
        out_vals + ((size_t)b * S_LEN + base + lq0) * D_DIM);
    #pragma unroll
    for (int q = 0; q < QW; ++q) {
        obase[q * 64 + 2 * lane]     = acc[q][0];
        obase[q * 64 + 2 * lane + 1] = acc[q][1];
    }
}

extern "C" void kernel_launch(void* const* d_in, const int* in_sizes, int n_in,
                              void* d_out, int out_size)
{
    const float* q    = (const float*)d_in[0];
    const float* k    = (const float*)d_in[1];
    const float* v    = (const float*)d_in[2];
    const int*   mask = (const int*)d_in[3];

    float* out_vals = (float*)d_out;
    float* out_p    = out_vals + (size_t)B_SZ * S_LEN * D_DIM;

    static bool attr_set = false;
    if (!attr_set) {
        cudaFuncSetAttribute(local_attn_kernel,
                             cudaFuncAttributeMaxDynamicSharedMemorySize,
                             SMEM_BYTES);
        attr_set = true;
    }

    dim3 grid(S_LEN / TILE_Q, B_SZ);   // (32, 4) = 128 CTAs, one wave
    local_attn_kernel<<<grid, THREADS, SMEM_BYTES>>>(q, k, v, mask, out_vals, out_p);
}

// round 16
// speedup vs baseline: 1.2194x; 1.2194x over previous
#include <cuda_runtime.h>
#include <cstddef>
#include <cstdint>

// LocalAttention: B=4, S=2048, D=256, W=33
// out = [values (B,S,D) | p_attn (B,S,W)] as float32
// Pass 1 (Q.K^T band scores) on TF32 tensor cores, 48 balanced half-tiles;
// softmax + PV scalar fp32.

#define S_LEN   2048
#define D_DIM   256
#define B_SZ    4
#define W_SZ    33
#define HALF_W  16
#define TILE_Q  64
#define THREADS 512                // 16 warps
#define QW      4                  // queries per softmax/pass2 warp
#define ROWS    (TILE_Q + 2*HALF_W)  // 96 K/V rows
#define NR      (QW + 2*HALF_W)    // 36 rows per pass2 warp
#define NW      (THREADS/32)       // 16 warps

#define QP      260                // padded floats per K/Q row (conflict-free frags)
#define QPC     65                 // 16B chunks per padded row
#define SROW    36                 // padded floats per score row
#define SBUF    (TILE_Q*SROW)      // one score buffer: 2304 floats

// smem float offsets
#define OFF_K   0                         // K:  96*260
#define OFF_U   (ROWS*QP)                 // Q (64 rows) then V (96 rows)
#define OFF_S   (OFF_U + ROWS*QP)         // scores: 2 buffers of 64*36
#define OFF_PF  (OFF_S + 2*SBUF)          // final p: [NW][NR][4]
#define OFF_F   (OFF_PF + NW*NR*4)        // flags: 96 ints
#define SMEM_FLOATS (OFF_F + ROWS)
#define SMEM_BYTES  (SMEM_FLOATS*4)

typedef unsigned long long ull;

__device__ __forceinline__ ull fma2(ull a, ull b, ull c) {
    ull d;
    asm("fma.rn.f32x2 %0, %1, %2, %3;" : "=l"(d) : "l"(a), "l"(b), "l"(c));
    return d;
}
__device__ __forceinline__ ull pack2(float x) {
    ull d;
    asm("mov.b64 %0, {%1, %1};" : "=l"(d) : "f"(x));
    return d;
}
__device__ __forceinline__ uint32_t cvt_tf32(float x) {
    uint32_t r;
    asm("cvt.rna.tf32.f32 %0, %1;" : "=r"(r) : "f"(x));
    return r;
}
__device__ __forceinline__ void mma_tf32(float& c0, float& c1, float& c2, float& c3,
                                         uint32_t a0, uint32_t a1, uint32_t a2, uint32_t a3,
                                         uint32_t b0, uint32_t b1) {
    asm volatile("mma.sync.aligned.m16n8k8.row.col.f32.tf32.tf32.f32 "
                 "{%0,%1,%2,%3}, {%4,%5,%6,%7}, {%8,%9}, {%0,%1,%2,%3};"
                 : "+f"(c0), "+f"(c1), "+f"(c2), "+f"(c3)
                 : "r"(a0), "r"(a1), "r"(a2), "r"(a3), "r"(b0), "r"(b1));
}
__device__ __forceinline__ void cp16(void* smem_dst, const void* gsrc) {
    uint32_t s = (uint32_t)__cvta_generic_to_shared(smem_dst);
    asm volatile("cp.async.cg.shared.global [%0], [%1], 16;" :: "r"(s), "l"(gsrc));
}

__global__ void __launch_bounds__(THREADS, 1)
local_attn_kernel(const float* __restrict__ qg,
                  const float* __restrict__ kg,
                  const float* __restrict__ vg,
                  const int*   __restrict__ maskg,
                  float* __restrict__ out_vals,
                  float* __restrict__ out_p)
{
    extern __shared__ float smem[];
    float4* sm4  = reinterpret_cast<float4*>(smem);
    float*  Ksmf = smem + OFF_K;
    float*  Usmf = smem + OFF_U;
    float*  Sbl  = smem + OFF_S;     // two buffers: +0 (K-half 0), +SBUF (K-half 1)
    float*  PF   = smem + OFF_PF;
    int*    Fsm  = reinterpret_cast<int*>(smem + OFF_F);

    const int tile = blockIdx.x;
    const int b    = blockIdx.y;
    const int base = tile * TILE_Q;
    const int r0   = base - HALF_W;
    const int tid  = threadIdx.x;

    const float4* kg4 = reinterpret_cast<const float4*>(kg + (size_t)b * S_LEN * D_DIM);
    const float4* vg4 = reinterpret_cast<const float4*>(vg + (size_t)b * S_LEN * D_DIM);
    const float4* qg4 = reinterpret_cast<const float4*>(qg + ((size_t)b * S_LEN + base) * D_DIM);

    // ---- async-stage K (rows clamped) into padded rows ----
    #pragma unroll
    for (int it = 0; it < ROWS * 64 / THREADS; ++it) {   // 12 iters
        int idx  = tid + it * THREADS;
        int row  = idx >> 6;
        int col  = idx & 63;
        int grow = r0 + row;
        int gcl  = grow < 0 ? 0 : (grow >= S_LEN ? S_LEN - 1 : grow);
        cp16(sm4 + row * QPC + col, kg4 + (size_t)gcl * 64 + col);
    }
    // ---- async-stage Q (64 rows) into U region ----
    #pragma unroll
    for (int it = 0; it < TILE_Q * 64 / THREADS; ++it) {  // 8 iters
        int idx = tid + it * THREADS;
        int row = idx >> 6;
        int col = idx & 63;
        cp16(sm4 + (OFF_U / 4) + row * QPC + col, qg4 + (size_t)row * 64 + col);
    }
    asm volatile("cp.async.commit_group;" ::: "memory");

    // ---- mask flags ----
    if (tid < ROWS) {
        int grow = r0 + tid;
        int f = 0;
        if (grow >= 0 && grow < S_LEN) f = (maskg[b * S_LEN + grow] != 0);
        Fsm[tid] = f;
    }

    const int warp = tid >> 5;
    const int lane = tid & 31;
    const int lq0  = warp * QW;
    float* pf = PF + warp * NR * 4;      // this warp's final p [NR][4]

    // zero final-p (out-of-window slots must read 0 in pass 2)
    #pragma unroll
    for (int i = lane; i < NR * 4; i += 32) pf[i] = 0.f;

    asm volatile("cp.async.wait_group 0;" ::: "memory");
    __syncthreads();

    // ---- pass 1: band GEMM, 48 half-tiles, 3 per warp, 8-deep mma chains ----
    // half-tile ht: tile = ht>>1 (qt = tile/6, q0 = 16qt, n0 = q0 + 8*(tile%6)),
    //               kh = ht&1 -> K dims [kh*128, kh*128+128)
    const int g  = lane >> 2;    // 0..7
    const int t4 = lane & 3;     // 0..3
    #pragma unroll
    for (int hi = 0; hi < 3; ++hi) {
        int ht = warp + hi * 16;          // 0..47
        int tl = ht >> 1;
        int kh = ht & 1;
        int qt = tl / 6;
        int q0 = qt * 16;
        int n0 = q0 + (tl % 6) * 8;
        float ca0 = 0.f, ca1 = 0.f, ca2 = 0.f, ca3 = 0.f;
        float cb0 = 0.f, cb1 = 0.f, cb2 = 0.f, cb3 = 0.f;
        const float* Qa  = Usmf + (q0 + g) * QP + t4 + kh * 128;
        const float* Qa8 = Qa + 8 * QP;
        const float* Kb  = Ksmf + (n0 + g) * QP + t4 + kh * 128;
        #pragma unroll 8
        for (int ks = 0; ks < 16; ks += 2) {
            int d0 = ks * 8;
            {
                uint32_t a0 = cvt_tf32(Qa[d0]);
                uint32_t a1 = cvt_tf32(Qa8[d0]);
                uint32_t a2 = cvt_tf32(Qa[d0 + 4]);
                uint32_t a3 = cvt_tf32(Qa8[d0 + 4]);
                uint32_t b0 = cvt_tf32(Kb[d0]);
                uint32_t b1 = cvt_tf32(Kb[d0 + 4]);
                mma_tf32(ca0, ca1, ca2, ca3, a0, a1, a2, a3, b0, b1);
            }
            {
                uint32_t a0 = cvt_tf32(Qa[d0 + 8]);
                uint32_t a1 = cvt_tf32(Qa8[d0 + 8]);
                uint32_t a2 = cvt_tf32(Qa[d0 + 12]);
                uint32_t a3 = cvt_tf32(Qa8[d0 + 12]);
                uint32_t b0 = cvt_tf32(Kb[d0 + 8]);
                uint32_t b1 = cvt_tf32(Kb[d0 + 12]);
                mma_tf32(cb0, cb1, cb2, cb3, a0, a1, a2, a3, b0, b1);
            }
        }
        float c0 = ca0 + cb0;
        float c1 = ca1 + cb1;
        float c2 = ca2 + cb2;
        float c3 = ca3 + cb3;

        // scatter raw band partials into this K-half's buffer
        float* Sh = Sbl + kh * SBUF;
        int q_l = q0 + g;
        int m0  = n0 + 2 * t4;
        int w;
        w = m0 - q_l;
        if (w >= 0 && w <= 32) Sh[q_l * SROW + w] = c0;
        w = m0 + 1 - q_l;
        if (w >= 0 && w <= 32) Sh[q_l * SROW + w] = c1;
        w = m0 - (q_l + 8);
        if (w >= 0 && w <= 32) Sh[(q_l + 8) * SROW + w] = c2;
        w = m0 + 1 - (q_l + 8);
        if (w >= 0 && w <= 32) Sh[(q_l + 8) * SROW + w] = c3;
    }
    __syncthreads();   // scores visible block-wide; Q reads done

    // ---- async-stage V over the Q region ----
    #pragma unroll
    for (int it = 0; it < ROWS * 64 / THREADS; ++it) {   // 12 iters
        int idx  = tid + it * THREADS;
        int row  = idx >> 6;
        int col  = idx & 63;
        int grow = r0 + row;
        int gcl  = grow < 0 ? 0 : (grow >= S_LEN ? S_LEN - 1 : grow);
        cp16(sm4 + (OFF_U / 4) + row * QPC + col, vg4 + (size_t)gcl * 64 + col);
    }
    asm volatile("cp.async.commit_group;" ::: "memory");

    // ---- warp-local softmax: 8 lanes per query (overlaps V flight) ----
    const int g8 = lane >> 3;
    const int j  = lane & 7;
    const int gq = base + lq0 + g8;
    {
        const float* sr0 = Sbl + (lq0 + g8) * SROW;
        const float* sr1 = sr0 + SBUF;
        const int*   fr  = Fsm + lq0 + g8;
        float s0 = fr[j]      ? (sr0[j]      + sr1[j])      * 0.0625f : -1e10f;
        float s1 = fr[j + 8]  ? (sr0[j + 8]  + sr1[j + 8])  * 0.0625f : -1e10f;
        float s2 = fr[j + 16] ? (sr0[j + 16] + sr1[j + 16]) * 0.0625f : -1e10f;
        float s3 = fr[j + 24] ? (sr0[j + 24] + sr1[j + 24]) * 0.0625f : -1e10f;
        float s4 = (j == 0) ? (fr[32] ? (sr0[32] + sr1[32]) * 0.0625f : -1e10f) : -3e38f;

        float mx = fmaxf(fmaxf(fmaxf(s0, s1), fmaxf(s2, s3)), s4);
        mx = fmaxf(mx, __shfl_xor_sync(0xffffffffu, mx, 4));
        mx = fmaxf(mx, __shfl_xor_sync(0xffffffffu, mx, 2));
        mx = fmaxf(mx, __shfl_xor_sync(0xffffffffu, mx, 1));

        float e0 = __expf(s0 - mx);
        float e1 = __expf(s1 - mx);
        float e2 = __expf(s2 - mx);
        float e3 = __expf(s3 - mx);
        float e4 = (j == 0) ? __expf(s4 - mx) : 0.f;

        float sum = ((e0 + e1) + (e2 + e3)) + e4;
        sum += __shfl_xor_sync(0xffffffffu, sum, 4);
        sum += __shfl_xor_sync(0xffffffffu, sum, 2);
        sum += __shfl_xor_sync(0xffffffffu, sum, 1);
        float inv = 1.f / sum;

        float p0 = e0 * inv, p1 = e1 * inv, p2 = e2 * inv, p3 = e3 * inv;
        int m0 = g8 + j;
        pf[m0 * 4 + g8]        = p0;
        pf[(m0 + 8) * 4 + g8]  = p1;
        pf[(m0 + 16) * 4 + g8] = p2;
        pf[(m0 + 24) * 4 + g8] = p3;

        float* po = out_p + (size_t)(b * S_LEN + gq) * W_SZ;
        po[j]      = p0;
        po[j + 8]  = p1;
        po[j + 16] = p2;
        po[j + 24] = p3;
        if (j == 0) {
            float p4 = e4 * inv;
            pf[(g8 + 32) * 4 + g8] = p4;
            po[32] = p4;
        }
    }

    // V resident + visible (and pf published) before pass 2
    asm volatile("cp.async.wait_group 0;" ::: "memory");
    __syncthreads();

    // ---- pass 2: scalar fp32x2, V rows + p float4 prefetched ----
    ulonglong2 acc[QW][2];
    #pragma unroll
    for (int q = 0; q < QW; ++q) {
        acc[q][0].x = 0ull; acc[q][0].y = 0ull;
        acc[q][1].x = 0ull; acc[q][1].y = 0ull;
    }

    const ulonglong2* Vsm2 = reinterpret_cast<const ulonglong2*>(Usmf);
    const float4* pf4 = reinterpret_cast<const float4*>(pf);

    ulonglong2 v0 = Vsm2[(size_t)lq0 * QPC + 2 * lane];
    ulonglong2 v1 = Vsm2[(size_t)lq0 * QPC + 2 * lane + 1];
    float4 pv = pf4[0];

    #pragma unroll 4
    for (int r = 0; r < NR; ++r) {   // 36
        ulonglong2 v0n, v1n;
        float4 pvn;
        if (r + 1 < NR) {
            const ulonglong2* vn = Vsm2 + (size_t)(lq0 + r + 1) * QPC + 2 * lane;
            v0n = vn[0];
            v1n = vn[1];
            pvn = pf4[r + 1];
        }
        ull pp0 = pack2(pv.x);
        ull pp1 = pack2(pv.y);
        ull pp2 = pack2(pv.z);
        ull pp3 = pack2(pv.w);
        acc[0][0].x = fma2(pp0, v0.x, acc[0][0].x);
        acc[0][0].y = fma2(pp0, v0.y, acc[0][0].y);
        acc[0][1].x = fma2(pp0, v1.x, acc[0][1].x);
        acc[0][1].y = fma2(pp0, v1.y, acc[0][1].y);
        acc[1][0].x = fma2(pp1, v0.x, acc[1][0].x);
        acc[1][0].y = fma2(pp1, v0.y, acc[1][0].y);
        acc[1][1].x = fma2(pp1, v1.x, acc[1][1].x);
        acc[1][1].y = fma2(pp1, v1.y, acc[1][1].y);
        acc[2][0].x = fma2(pp2, v0.x, acc[2][0].x);
        acc[2][0].y = fma2(pp2, v0.y, acc[2][0].y);
        acc[2][1].x = fma2(pp2, v1.x, acc[2][1].x);
        acc[2][1].y = fma2(pp2, v1.y, acc[2][1].y);
        acc[3][0].x = fma2(pp3, v0.x, acc[3][0].x);
        acc[3][0].y = fma2(pp3, v0.y, acc[3][0].y);
        acc[3][1].x = fma2(pp3, v1.x, acc[3][1].x);
        acc[3][1].y = fma2(pp3, v1.y, acc[3][1].y);
        v0 = v0n;
        v1 = v1n;
        pv = pvn;
    }

    ulonglong2* obase = reinterpret_cast<ulonglong2*>(
        out_vals + ((size_t)b * S_LEN + base + lq0) * D_DIM);
    #pragma unroll
    for (int q = 0; q < QW; ++q) {
        obase[q * 64 + 2 * lane]     = acc[q][0];
        obase[q * 64 + 2 * lane + 1] = acc[q][1];
    }
}

extern "C" void kernel_launch(void* const* d_in, const int* in_sizes, int n_in,
                              void* d_out, int out_size)
{
    const float* q    = (const float*)d_in[0];
    const float* k    = (const float*)d_in[1];
    const float* v    = (const float*)d_in[2];
    const int*   mask = (const int*)d_in[3];

    float* out_vals = (float*)d_out;
    float* out_p    = out_vals + (size_t)B_SZ * S_LEN * D_DIM;

    static bool attr_set = false;
    if (!attr_set) {
        cudaFuncSetAttribute(local_attn_kernel,
                             cudaFuncAttributeMaxDynamicSharedMemorySize,
                             SMEM_BYTES);
        attr_set = true;
    }

    dim3 grid(S_LEN / TILE_Q, B_SZ);   // (32, 4) = 128 CTAs, one wave
    local_attn_kernel<<<grid, THREADS, SMEM_BYTES>>>(q, k, v, mask, out_vals, out_p);
}

// round 17
// speedup vs baseline: 1.5128x; 1.2406x over previous
#include <cuda_runtime.h>
#include <cstddef>
#include <cstdint>

// LocalAttention: B=4, S=2048, D=256, W=33
// out = [values (B,S,D) | p_attn (B,S,W)] as float32
// Pass 1: TF32 tensor-core band GEMM with k-permuted float4 fragment loads
//         and XOR-swizzled smem (conflict-free, no row padding).
// Softmax + PV scalar fp32x2.

#define S_LEN   2048
#define D_DIM   256
#define B_SZ    4
#define W_SZ    33
#define HALF_W  16
#define TILE_Q  64
#define THREADS 512                // 16 warps
#define QW      4                  // queries per softmax/pass2 warp
#define ROWS    (TILE_Q + 2*HALF_W)  // 96 K/V rows
#define NR      (QW + 2*HALF_W)    // 36 rows per pass2 warp
#define NW      (THREADS/32)       // 16 warps

#define RC      64                 // 16B chunks per row (256 floats, no padding)
#define SROW    36                 // floats per score row
#define SBUF    (TILE_Q*SROW)      // one score buffer

// smem float offsets
#define OFF_K   0                          // K: 96*256
#define OFF_U   (ROWS*256)                 // Q (64 rows) then V (96 rows)
#define OFF_S   (OFF_U + ROWS*256)         // scores: 2 buffers
#define OFF_PF  (OFF_S + 2*SBUF)           // final p: [NW][NR][4]
#define OFF_F   (OFF_PF + NW*NR*4)         // flags: 96 ints
#define SMEM_FLOATS (OFF_F + ROWS)
#define SMEM_BYTES  (SMEM_FLOATS*4)

// 16B-chunk swizzle: phys_chunk = chunk ^ ((row&1)<<2)
#define SWZ(row) (((row) & 1) << 2)

typedef unsigned long long ull;

__device__ __forceinline__ ull fma2(ull a, ull b, ull c) {
    ull d;
    asm("fma.rn.f32x2 %0, %1, %2, %3;" : "=l"(d) : "l"(a), "l"(b), "l"(c));
    return d;
}
__device__ __forceinline__ ull pack2(float x) {
    ull d;
    asm("mov.b64 %0, {%1, %1};" : "=l"(d) : "f"(x));
    return d;
}
__device__ __forceinline__ uint32_t cvt_tf32(float x) {
    uint32_t r;
    asm("cvt.rna.tf32.f32 %0, %1;" : "=r"(r) : "f"(x));
    return r;
}
__device__ __forceinline__ void mma_tf32(float& c0, float& c1, float& c2, float& c3,
                                         uint32_t a0, uint32_t a1, uint32_t a2, uint32_t a3,
                                         uint32_t b0, uint32_t b1) {
    asm volatile("mma.sync.aligned.m16n8k8.row.col.f32.tf32.tf32.f32 "
                 "{%0,%1,%2,%3}, {%4,%5,%6,%7}, {%8,%9}, {%0,%1,%2,%3};"
                 : "+f"(c0), "+f"(c1), "+f"(c2), "+f"(c3)
                 : "r"(a0), "r"(a1), "r"(a2), "r"(a3), "r"(b0), "r"(b1));
}
__device__ __forceinline__ void cp16(void* smem_dst, const void* gsrc) {
    uint32_t s = (uint32_t)__cvta_generic_to_shared(smem_dst);
    asm volatile("cp.async.cg.shared.global [%0], [%1], 16;" :: "r"(s), "l"(gsrc));
}

__global__ void __launch_bounds__(THREADS, 1)
local_attn_kernel(const float* __restrict__ qg,
                  const float* __restrict__ kg,
                  const float* __restrict__ vg,
                  const int*   __restrict__ maskg,
                  float* __restrict__ out_vals,
                  float* __restrict__ out_p)
{
    extern __shared__ float smem[];
    float4* sm4 = reinterpret_cast<float4*>(smem);
    float*  Sbl = smem + OFF_S;     // two buffers: +0 (K-half 0), +SBUF (K-half 1)
    float*  PF  = smem + OFF_PF;
    int*    Fsm = reinterpret_cast<int*>(smem + OFF_F);

    const int tile = blockIdx.x;
    const int b    = blockIdx.y;
    const int base = tile * TILE_Q;
    const int r0   = base - HALF_W;
    const int tid  = threadIdx.x;

    const float4* kg4 = reinterpret_cast<const float4*>(kg + (size_t)b * S_LEN * D_DIM);
    const float4* vg4 = reinterpret_cast<const float4*>(vg + (size_t)b * S_LEN * D_DIM);
    const float4* qg4 = reinterpret_cast<const float4*>(qg + ((size_t)b * S_LEN + base) * D_DIM);

    // ---- async-stage K (rows clamped) swizzled ----
    #pragma unroll
    for (int it = 0; it < ROWS * RC / THREADS; ++it) {   // 12 iters
        int idx  = tid + it * THREADS;
        int row  = idx >> 6;
        int col  = idx & 63;
        int grow = r0 + row;
        int gcl  = grow < 0 ? 0 : (grow >= S_LEN ? S_LEN - 1 : grow);
        cp16(sm4 + row * RC + (col ^ SWZ(row)), kg4 + (size_t)gcl * RC + col);
    }
    // ---- async-stage Q (64 rows) swizzled into U region ----
    #pragma unroll
    for (int it = 0; it < TILE_Q * RC / THREADS; ++it) {  // 8 iters
        int idx = tid + it * THREADS;
        int row = idx >> 6;
        int col = idx & 63;
        cp16(sm4 + (OFF_U / 4) + row * RC + (col ^ SWZ(row)), qg4 + (size_t)row * RC + col);
    }
    asm volatile("cp.async.commit_group;" ::: "memory");

    // ---- mask flags ----
    if (tid < ROWS) {
        int grow = r0 + tid;
        int f = 0;
        if (grow >= 0 && grow < S_LEN) f = (maskg[b * S_LEN + grow] != 0);
        Fsm[tid] = f;
    }

    const int warp = tid >> 5;
    const int lane = tid & 31;
    const int lq0  = warp * QW;
    float* pf = PF + warp * NR * 4;      // this warp's final p [NR][4]

    // zero final-p (out-of-window slots must read 0 in pass 2)
    #pragma unroll
    for (int i = lane; i < NR * 4; i += 32) pf[i] = 0.f;

    asm volatile("cp.async.wait_group 0;" ::: "memory");
    __syncthreads();

    // ---- pass 1: band GEMM, 48 half-tiles, 3 per warp ----
    // half-tile ht: tile = ht>>1 (qt = tile/6, q0 = 16qt, n0 = q0+8*(tile%6)),
    //               kh = ht&1 -> chunk range [kh*32, kh*32+32)
    // k-permutation: per chunk (float4) loaded, mma#0 takes (.x,.y), mma#1 (.z,.w).
    const int g  = lane >> 2;    // 0..7
    const int t4 = lane & 3;     // 0..3
    const int sw = SWZ(g);       // all frag rows share parity of g
    #pragma unroll
    for (int hi = 0; hi < 3; ++hi) {
        int ht = warp + hi * 16;          // 0..47
        int tl = ht >> 1;
        int kh = ht & 1;
        int qt = tl / 6;
        int q0 = qt * 16;
        int n0 = q0 + (tl % 6) * 8;
        float ca0 = 0.f, ca1 = 0.f, ca2 = 0.f, ca3 = 0.f;
        float cb0 = 0.f, cb1 = 0.f, cb2 = 0.f, cb3 = 0.f;
        const float4* Qrow  = sm4 + (OFF_U / 4) + (q0 + g) * RC;
        const float4* Qrow8 = Qrow + 8 * RC;
        const float4* Krow  = sm4 + (n0 + g) * RC;
        #pragma unroll
        for (int kss = 0; kss < 8; ++kss) {
            int c = (kh * 32 + kss * 4 + t4) ^ sw;
            float4 fq  = Qrow[c];
            float4 fq8 = Qrow8[c];
            float4 fk  = Krow[c];
            mma_tf32(ca0, ca1, ca2, ca3,
                     cvt_tf32(fq.x), cvt_tf32(fq8.x), cvt_tf32(fq.y), cvt_tf32(fq8.y),
                     cvt_tf32(fk.x), cvt_tf32(fk.y));
            mma_tf32(cb0, cb1, cb2, cb3,
                     cvt_tf32(fq.z), cvt_tf32(fq8.z), cvt_tf32(fq.w), cvt_tf32(fq8.w),
                     cvt_tf32(fk.z), cvt_tf32(fk.w));
        }
        float c0 = ca0 + cb0;
        float c1 = ca1 + cb1;
        float c2 = ca2 + cb2;
        float c3 = ca3 + cb3;

        // scatter raw band partials into this K-half's buffer
        float* Sh = Sbl + kh * SBUF;
        int q_l = q0 + g;
        int m0  = n0 + 2 * t4;
        int w;
        w = m0 - q_l;
        if (w >= 0 && w <= 32) Sh[q_l * SROW + w] = c0;
        w = m0 + 1 - q_l;
        if (w >= 0 && w <= 32) Sh[q_l * SROW + w] = c1;
        w = m0 - (q_l + 8);
        if (w >= 0 && w <= 32) Sh[(q_l + 8) * SROW + w] = c2;
        w = m0 + 1 - (q_l + 8);
        if (w >= 0 && w <= 32) Sh[(q_l + 8) * SROW + w] = c3;
    }
    __syncthreads();   // scores visible block-wide; Q reads done

    // ---- async-stage V (96 rows, swizzled) over the Q region ----
    #pragma unroll
    for (int it = 0; it < ROWS * RC / THREADS; ++it) {   // 12 iters
        int idx  = tid + it * THREADS;
        int row  = idx >> 6;
        int col  = idx & 63;
        int grow = r0 + row;
        int gcl  = grow < 0 ? 0 : (grow >= S_LEN ? S_LEN - 1 : grow);
        cp16(sm4 + (OFF_U / 4) + row * RC + (col ^ SWZ(row)), vg4 + (size_t)gcl * RC + col);
    }
    asm volatile("cp.async.commit_group;" ::: "memory");

    // ---- warp-local softmax: 8 lanes per query (overlaps V flight) ----
    const int g8 = lane >> 3;
    const int j  = lane & 7;
    const int gq = base + lq0 + g8;
    {
        const float* sr0 = Sbl + (lq0 + g8) * SROW;
        const float* sr1 = sr0 + SBUF;
        const int*   fr  = Fsm + lq0 + g8;
        float s0 = fr[j]      ? (sr0[j]      + sr1[j])      * 0.0625f : -1e10f;
        float s1 = fr[j + 8]  ? (sr0[j + 8]  + sr1[j + 8])  * 0.0625f : -1e10f;
        float s2 = fr[j + 16] ? (sr0[j + 16] + sr1[j + 16]) * 0.0625f : -1e10f;
        float s3 = fr[j + 24] ? (sr0[j + 24] + sr1[j + 24]) * 0.0625f : -1e10f;
        float s4 = (j == 0) ? (fr[32] ? (sr0[32] + sr1[32]) * 0.0625f : -1e10f) : -3e38f;

        float mx = fmaxf(fmaxf(fmaxf(s0, s1), fmaxf(s2, s3)), s4);
        mx = fmaxf(mx, __shfl_xor_sync(0xffffffffu, mx, 4));
        mx = fmaxf(mx, __shfl_xor_sync(0xffffffffu, mx, 2));
        mx = fmaxf(mx, __shfl_xor_sync(0xffffffffu, mx, 1));

        float e0 = __expf(s0 - mx);
        float e1 = __expf(s1 - mx);
        float e2 = __expf(s2 - mx);
        float e3 = __expf(s3 - mx);
        float e4 = (j == 0) ? __expf(s4 - mx) : 0.f;

        float sum = ((e0 + e1) + (e2 + e3)) + e4;
        sum += __shfl_xor_sync(0xffffffffu, sum, 4);
        sum += __shfl_xor_sync(0xffffffffu, sum, 2);
        sum += __shfl_xor_sync(0xffffffffu, sum, 1);
        float inv = 1.f / sum;

        float p0 = e0 * inv, p1 = e1 * inv, p2 = e2 * inv, p3 = e3 * inv;
        int m0 = g8 + j;
        pf[m0 * 4 + g8]        = p0;
        pf[(m0 + 8) * 4 + g8]  = p1;
        pf[(m0 + 16) * 4 + g8] = p2;
        pf[(m0 + 24) * 4 + g8] = p3;

        float* po = out_p + (size_t)(b * S_LEN + gq) * W_SZ;
        po[j]      = p0;
        po[j + 8]  = p1;
        po[j + 16] = p2;
        po[j + 24] = p3;
        if (j == 0) {
            float p4 = e4 * inv;
            pf[(g8 + 32) * 4 + g8] = p4;
            po[32] = p4;
        }
    }

    // V resident + visible (and pf published) before pass 2
    asm volatile("cp.async.wait_group 0;" ::: "memory");
    __syncthreads();

    // ---- pass 2: lane owns chunks (lane, lane+32); conflict-free swizzled loads ----
    ulonglong2 acc[QW][2];
    #pragma unroll
    for (int q = 0; q < QW; ++q) {
        acc[q][0].x = 0ull; acc[q][0].y = 0ull;
        acc[q][1].x = 0ull; acc[q][1].y = 0ull;
    }

    const ulonglong2* Vsm2 = reinterpret_cast<const ulonglong2*>(smem + OFF_U);
    const float4* pf4 = reinterpret_cast<const float4*>(pf);

    ulonglong2 v0 = Vsm2[(size_t)lq0 * RC + (lane ^ SWZ(lq0))];
    ulonglong2 v1 = Vsm2[(size_t)lq0 * RC + ((lane + 32) ^ SWZ(lq0))];
    float4 pv = pf4[0];

    #pragma unroll 4
    for (int r = 0; r < NR; ++r) {   // 36
        ulonglong2 v0n, v1n;
        float4 pvn;
        if (r + 1 < NR) {
            int m = lq0 + r + 1;
            const ulonglong2* vr = Vsm2 + (size_t)m * RC;
            v0n = vr[lane ^ SWZ(m)];
            v1n = vr[(lane + 32) ^ SWZ(m)];
            pvn = pf4[r + 1];
        }
        ull pp0 = pack2(pv.x);
        ull pp1 = pack2(pv.y);
        ull pp2 = pack2(pv.z);
        ull pp3 = pack2(pv.w);
        acc[0][0].x = fma2(pp0, v0.x, acc[0][0].x);
        acc[0][0].y = fma2(pp0, v0.y, acc[0][0].y);
        acc[0][1].x = fma2(pp0, v1.x, acc[0][1].x);
        acc[0][1].y = fma2(pp0, v1.y, acc[0][1].y);
        acc[1][0].x = fma2(pp1, v0.x, acc[1][0].x);
        acc[1][0].y = fma2(pp1, v0.y, acc[1][0].y);
        acc[1][1].x = fma2(pp1, v1.x, acc[1][1].x);
        acc[1][1].y = fma2(pp1, v1.y, acc[1][1].y);
        acc[2][0].x = fma2(pp2, v0.x, acc[2][0].x);
        acc[2][0].y = fma2(pp2, v0.y, acc[2][0].y);
        acc[2][1].x = fma2(pp2, v1.x, acc[2][1].x);
        acc[2][1].y = fma2(pp2, v1.y, acc[2][1].y);
        acc[3][0].x = fma2(pp3, v0.x, acc[3][0].x);
        acc[3][0].y = fma2(pp3, v0.y, acc[3][0].y);
        acc[3][1].x = fma2(pp3, v1.x, acc[3][1].x);
        acc[3][1].y = fma2(pp3, v1.y, acc[3][1].y);
        v0 = v0n;
        v1 = v1n;
        pv = pvn;
    }

    float4* obase = reinterpret_cast<float4*>(
        out_vals + ((size_t)b * S_LEN + base + lq0) * D_DIM);
    const float4* accf = reinterpret_cast<const float4*>(acc);
    #pragma unroll
    for (int q = 0; q < QW; ++q) {
        obase[q * RC + lane]      = accf[q * 2];
        obase[q * RC + lane + 32] = accf[q * 2 + 1];
    }
}

extern "C" void kernel_launch(void* const* d_in, const int* in_sizes, int n_in,
                              void* d_out, int out_size)
{
    const float* q    = (const float*)d_in[0];
    const float* k    = (const float*)d_in[1];
    const float* v    = (const float*)d_in[2];
    const int*   mask = (const int*)d_in[3];

    float* out_vals = (float*)d_out;
    float* out_p    = out_vals + (size_t)B_SZ * S_LEN * D_DIM;

    static bool attr_set = false;
    if (!attr_set) {
        cudaFuncSetAttribute(local_attn_kernel,
                             cudaFuncAttributeMaxDynamicSharedMemorySize,
                             SMEM_BYTES);
        attr_set = true;
    }

    dim3 grid(S_LEN / TILE_Q, B_SZ);   // (32, 4) = 128 CTAs, one wave
    local_attn_kernel<<<grid, THREADS, SMEM_BYTES>>>(q, k, v, mask, out_vals, out_p);
}